// round 7
// baseline (speedup 1.0000x reference)
#include <cuda_runtime.h>
#include <cuda_fp16.h>
#include <math.h>
#include <stdint.h>

#define SS 2048
#define RR 512
#define NT 256
#define MHW 36    // m row stride in words (72 halves); 36 % 32 == 4 -> frag gather conflict-free

// ---- shared memory layout (32-bit word offsets) ----
static constexpr int OFF_M    = 0;                    // fp16 m: 512*36 = 18432
static constexpr int OFF_WGF  = 18432;                // Wg B-frags 2048
static constexpr int OFF_WOF  = OFF_WGF + 2048;       // Wo frags 2048
static constexpr int OFF_WKF  = OFF_WOF + 2048;       // Wk frags 256
static constexpr int OFF_WVF  = OFF_WKF + 256;        // Wv frags 256
static constexpr int OFF_KV   = OFF_WVF + 256;        // 512 rows * 9: K(4xh2) V(4xh2) bias(f32)
static constexpr int OFF_MASK = OFF_KV + RR * 9;      // 512
static constexpr int OFF_PART = OFF_MASK + 512;       // 8 warps * 64
static constexpr int OFF_POOL = OFF_PART + 512;       // 64 scratch (redundant identical writes)
static constexpr int OFF_QH   = OFF_POOL + 64;        // 64
static constexpr int OFF_OF   = OFF_QH + 64;          // 64
static constexpr int OFF_BG   = OFF_OF + 64;
static constexpr int OFF_BO   = OFF_BG + 64;
static constexpr int SMEM_WORDS = OFF_BO + 64;        // 29056
static constexpr int SMEM_BYTES = SMEM_WORDS * 4;     // 116224 B -> 2 CTAs/SM

__device__ __forceinline__ uint32_t packh2(float lo, float hi) {
    __half2 h = __floats2half2_rn(lo, hi);
    return *(uint32_t*)&h;
}
__device__ __forceinline__ float2 h2f2(uint32_t u) {
    return __half22float2(*(__half2*)&u);
}
__device__ __forceinline__ void mma_f16(float c[4], const uint32_t a[4],
                                        uint32_t b0, uint32_t b1)
{
    asm("mma.sync.aligned.m16n8k16.row.col.f32.f16.f16.f32 "
        "{%0,%1,%2,%3}, {%4,%5,%6,%7}, {%8,%9}, {%0,%1,%2,%3};"
        : "+f"(c[0]), "+f"(c[1]), "+f"(c[2]), "+f"(c[3])
        : "r"(a[0]), "r"(a[1]), "r"(a[2]), "r"(a[3]), "r"(b0), "r"(b1));
}

__global__ void __launch_bounds__(NT, 2) ga_kernel(
    const float* __restrict__ m, const float* __restrict__ mask,
    const float* __restrict__ Wq, const float* __restrict__ Wk,
    const float* __restrict__ Wv, const float* __restrict__ Wg,
    const float* __restrict__ bg, const float* __restrict__ Wo,
    const float* __restrict__ bo, float* __restrict__ out)
{
    extern __shared__ float sm[];
    uint32_t* smu = (uint32_t*)sm;
    const int s    = blockIdx.x;
    const int tid  = threadIdx.x;
    const int warp = tid >> 5, lane = tid & 31;
    const int qrow = lane >> 2, qcol = lane & 3;
    const float* m_s    = m + (size_t)s * (RR * 64);
    const float* mask_g = mask + (size_t)s * RR;

    // ---------- Phase 0: stage m fp16 + pool partials + bias + weight frags ----------
    {
        const float4* m4 = (const float4*)m_s;
        const int cg4 = tid & 15, rbase = tid >> 4;
        float px = 0.f, py = 0.f, pz = 0.f, pw = 0.f;
        #pragma unroll
        for (int j = 0; j < 32; ++j) {
            int r = rbase + j * 16;
            float4 v = m4[r * 16 + cg4];
            float mk = __ldg(mask_g + r);
            px += v.x * mk; py += v.y * mk; pz += v.z * mk; pw += v.w * mk;
            smu[OFF_M + r * MHW + cg4 * 2]     = packh2(v.x, v.y);
            smu[OFF_M + r * MHW + cg4 * 2 + 1] = packh2(v.z, v.w);
        }
        px += __shfl_down_sync(0xFFFFFFFFu, px, 16);
        py += __shfl_down_sync(0xFFFFFFFFu, py, 16);
        pz += __shfl_down_sync(0xFFFFFFFFu, pz, 16);
        pw += __shfl_down_sync(0xFFFFFFFFu, pw, 16);
        if (lane < 16) {
            float4 pp; pp.x = px; pp.y = py; pp.z = pz; pp.w = pw;
            *(float4*)&sm[OFF_PART + warp * 64 + cg4 * 4] = pp;
        }
        #pragma unroll
        for (int i = tid; i < RR; i += NT) {
            float mk = __ldg(mask_g + i);
            sm[OFF_MASK + i] = mk;
            sm[OFF_KV + i * 9 + 8] = 1e9f * (mk - 1.0f);   // softmax bias
        }
        if (tid < 64) { sm[OFF_BG + tid] = bg[tid]; sm[OFF_BO + tid] = bo[tid]; }

        // B-fragments (m16n8k16.row.col): b0={W[k0][n],W[k0+1][n]}, b1={W[k0+8][n],W[k0+9][n]},
        // k0 = ktg*16 + 2*qcol, n = nt*8 + qrow
        #pragma unroll
        for (int it = 0; it < 4; ++it) {
            int idx = it * 8 + warp;          // 0..31 -> (nt, ktg)
            int nt = idx >> 2, ktg = idx & 3;
            int d0 = ktg * 16 + 2 * qcol;
            int cc = nt * 8 + qrow;
            int off = ((nt * 4 + ktg) * 32 + lane) * 2;
            smu[OFF_WGF + off]     = packh2(Wg[d0 * 64 + cc],       Wg[(d0 + 1) * 64 + cc]);
            smu[OFF_WGF + off + 1] = packh2(Wg[(d0 + 8) * 64 + cc], Wg[(d0 + 9) * 64 + cc]);
            smu[OFF_WOF + off]     = packh2(Wo[d0 * 64 + cc],       Wo[(d0 + 1) * 64 + cc]);
            smu[OFF_WOF + off + 1] = packh2(Wo[(d0 + 8) * 64 + cc], Wo[(d0 + 9) * 64 + cc]);
        }
        if (warp < 4) {
            int ktg = warp;
            int d0 = ktg * 16 + 2 * qcol;
            int off = (ktg * 32 + lane) * 2;
            smu[OFF_WKF + off]     = packh2(Wk[d0 * 8 + qrow],       Wk[(d0 + 1) * 8 + qrow]);
            smu[OFF_WKF + off + 1] = packh2(Wk[(d0 + 8) * 8 + qrow], Wk[(d0 + 9) * 8 + qrow]);
            smu[OFF_WVF + off]     = packh2(Wv[d0 * 8 + qrow],       Wv[(d0 + 1) * 8 + qrow]);
            smu[OFF_WVF + off + 1] = packh2(Wv[(d0 + 8) * 8 + qrow], Wv[(d0 + 9) * 8 + qrow]);
        }
    }
    __syncthreads();   // B1: m, PART, frags, bias ready

    // ================= each warp owns 64 rows r0..r0+63; warp = head =================
    const int r0 = warp * 64;

    // ---------- Phase 1: per-warp pool + q (redundant across warps; PART ready) ----------
    float qv[8];
    {
        float p0 = 0.f, p1 = 0.f;
        #pragma unroll
        for (int w = 0; w < 8; ++w) {
            p0 += sm[OFF_PART + w * 64 + lane];
            p1 += sm[OFF_PART + w * 64 + lane + 32];
        }
        sm[OFF_POOL + lane]      = p0;   // all warps write identical values (benign)
        sm[OFF_POOL + lane + 32] = p1;
        float ms = 0.f;
        #pragma unroll
        for (int j = 0; j < 16; ++j) ms += sm[OFF_MASK + lane + 32 * j];
        #pragma unroll
        for (int o = 16; o; o >>= 1) ms += __shfl_xor_sync(0xFFFFFFFFu, ms, o);
        __syncwarp();
        const int c = lane & 7, qr = lane >> 3;   // lane -> (col, d-quarter)
        float acc = 0.f;
        #pragma unroll
        for (int dd = 0; dd < 16; ++dd) {
            int d = qr * 16 + dd;
            acc += sm[OFF_POOL + d] * __ldg(&Wq[d * 64 + warp * 8 + c]);
        }
        acc += __shfl_xor_sync(0xFFFFFFFFu, acc, 8);
        acc += __shfl_xor_sync(0xFFFFFFFFu, acc, 16);
        float qs = 0.35355339059327373f / (ms + 1e-10f);
        if (lane < 8) sm[OFF_QH + warp * 8 + lane] = acc * qs;
        __syncwarp();
        #pragma unroll
        for (int cc = 0; cc < 8; ++cc) qv[cc] = sm[OFF_QH + warp * 8 + cc];
    }

    // ---------- Phase 2: k = m@Wk, v = m@Wv via mma (A-frags from smem) ----------
    {
        uint32_t Af[4][4][4];
        #pragma unroll
        for (int mt = 0; mt < 4; ++mt)
            #pragma unroll
            for (int ktg = 0; ktg < 4; ++ktg) {
                int w = OFF_M + (r0 + mt * 16 + qrow) * MHW + ktg * 8 + qcol;
                Af[mt][ktg][0] = smu[w];
                Af[mt][ktg][1] = smu[w + 8 * MHW];
                Af[mt][ktg][2] = smu[w + 4];
                Af[mt][ktg][3] = smu[w + 8 * MHW + 4];
            }
        uint32_t b[4][2];
        #pragma unroll
        for (int ktg = 0; ktg < 4; ++ktg) {
            b[ktg][0] = smu[OFF_WKF + (ktg * 32 + lane) * 2];
            b[ktg][1] = smu[OFF_WKF + (ktg * 32 + lane) * 2 + 1];
        }
        float ck[4][4] = {{0,0,0,0},{0,0,0,0},{0,0,0,0},{0,0,0,0}};
        #pragma unroll
        for (int ktg = 0; ktg < 4; ++ktg)
            #pragma unroll
            for (int mt = 0; mt < 4; ++mt)
                mma_f16(ck[mt], Af[mt][ktg], b[ktg][0], b[ktg][1]);
        #pragma unroll
        for (int mt = 0; mt < 4; ++mt) {
            int row = r0 + mt * 16 + qrow;
            smu[OFF_KV + row * 9 + qcol]       = packh2(ck[mt][0], ck[mt][1]);
            smu[OFF_KV + (row + 8) * 9 + qcol] = packh2(ck[mt][2], ck[mt][3]);
        }
        #pragma unroll
        for (int ktg = 0; ktg < 4; ++ktg) {
            b[ktg][0] = smu[OFF_WVF + (ktg * 32 + lane) * 2];
            b[ktg][1] = smu[OFF_WVF + (ktg * 32 + lane) * 2 + 1];
        }
        float cv[4][4] = {{0,0,0,0},{0,0,0,0},{0,0,0,0},{0,0,0,0}};
        #pragma unroll
        for (int ktg = 0; ktg < 4; ++ktg)
            #pragma unroll
            for (int mt = 0; mt < 4; ++mt)
                mma_f16(cv[mt], Af[mt][ktg], b[ktg][0], b[ktg][1]);
        #pragma unroll
        for (int mt = 0; mt < 4; ++mt) {
            int row = r0 + mt * 16 + qrow;
            smu[OFF_KV + row * 9 + 4 + qcol]       = packh2(cv[mt][0], cv[mt][1]);
            smu[OFF_KV + (row + 8) * 9 + 4 + qcol] = packh2(cv[mt][2], cv[mt][3]);
        }
    }
    __syncthreads();   // B2: KV ready

    // ---------- Phase 3: attention (warp = head; bias -1e9 kills masked rows) ----------
    {
        float sum = 0.f;
        float oa[8] = {0,0,0,0,0,0,0,0};
        #pragma unroll
        for (int i = 0; i < 16; ++i) {
            int r = i * 32 + lane;
            const uint32_t* kv = smu + OFF_KV + r * 9;
            float2 k0 = h2f2(kv[0]), k1 = h2f2(kv[1]), k2 = h2f2(kv[2]), k3 = h2f2(kv[3]);
            float bias = sm[OFF_KV + r * 9 + 8];
            float a = qv[0]*k0.x + qv[1]*k0.y + qv[2]*k1.x + qv[3]*k1.y
                    + qv[4]*k2.x + qv[5]*k2.y + qv[6]*k3.x + qv[7]*k3.y + bias;
            float p = __expf(a);
            sum += p;
            float2 v0 = h2f2(kv[4]), v1 = h2f2(kv[5]), v2 = h2f2(kv[6]), v3 = h2f2(kv[7]);
            oa[0] += p * v0.x; oa[1] += p * v0.y; oa[2] += p * v1.x; oa[3] += p * v1.y;
            oa[4] += p * v2.x; oa[5] += p * v2.y; oa[6] += p * v3.x; oa[7] += p * v3.y;
        }
        #pragma unroll
        for (int o = 16; o; o >>= 1) sum += __shfl_xor_sync(0xFFFFFFFFu, sum, o);
        #pragma unroll
        for (int c = 0; c < 8; ++c) {
            #pragma unroll
            for (int o = 16; o; o >>= 1) oa[c] += __shfl_xor_sync(0xFFFFFFFFu, oa[c], o);
        }
        if (lane == 0) {
            float inv = 1.f / sum;
            #pragma unroll
            for (int c = 0; c < 8; ++c) sm[OFF_OF + warp * 8 + c] = oa[c] * inv;
        }
    }
    __syncthreads();   // B3: OF ready for all warps

    // ---------- Phase 4: gate + output GEMM; h register-resident (acc -> A-frag identity) ----------
    // Two 32-row halves to bound live registers: Af-half (32) + Ah-half (32).
    float* outs = out + (size_t)s * (RR * 64);
    #pragma unroll
    for (int mh = 0; mh < 2; ++mh) {
        uint32_t Am[2][4][4];
        #pragma unroll
        for (int mt2 = 0; mt2 < 2; ++mt2)
            #pragma unroll
            for (int ktg = 0; ktg < 4; ++ktg) {
                int w = OFF_M + (r0 + (mh * 2 + mt2) * 16 + qrow) * MHW + ktg * 8 + qcol;
                Am[mt2][ktg][0] = smu[w];
                Am[mt2][ktg][1] = smu[w + 8 * MHW];
                Am[mt2][ktg][2] = smu[w + 4];
                Am[mt2][ktg][3] = smu[w + 8 * MHW + 4];
            }

        uint32_t Ah[2][4][4];
        #pragma unroll
        for (int kh = 0; kh < 4; ++kh) {
            #pragma unroll
            for (int sub = 0; sub < 2; ++sub) {
                const int nt = 2 * kh + sub;
                float cg[2][4] = {{0,0,0,0},{0,0,0,0}};
                #pragma unroll
                for (int ktg = 0; ktg < 4; ++ktg) {
                    uint32_t b0 = smu[OFF_WGF + ((nt * 4 + ktg) * 32 + lane) * 2];
                    uint32_t b1 = smu[OFF_WGF + ((nt * 4 + ktg) * 32 + lane) * 2 + 1];
                    #pragma unroll
                    for (int mt2 = 0; mt2 < 2; ++mt2)
                        mma_f16(cg[mt2], Am[mt2][ktg], b0, b1);
                }
                const int col0 = nt * 8 + 2 * qcol;
                float of0 = sm[OFF_OF + col0], of1 = sm[OFF_OF + col0 + 1];
                float bg0 = sm[OFF_BG + col0], bg1 = sm[OFF_BG + col0 + 1];
                #pragma unroll
                for (int mt2 = 0; mt2 < 2; ++mt2) {
                    float h0 = of0 / (1.f + __expf(-(cg[mt2][0] + bg0)));
                    float h1 = of1 / (1.f + __expf(-(cg[mt2][1] + bg1)));
                    float h2 = of0 / (1.f + __expf(-(cg[mt2][2] + bg0)));
                    float h3 = of1 / (1.f + __expf(-(cg[mt2][3] + bg1)));
                    Ah[mt2][kh][sub * 2]     = packh2(h0, h1);
                    Ah[mt2][kh][sub * 2 + 1] = packh2(h2, h3);
                }
            }
        }
        #pragma unroll
        for (int nt = 0; nt < 8; ++nt) {
            float co[2][4] = {{0,0,0,0},{0,0,0,0}};
            #pragma unroll
            for (int kh = 0; kh < 4; ++kh) {
                uint32_t b0 = smu[OFF_WOF + ((nt * 4 + kh) * 32 + lane) * 2];
                uint32_t b1 = smu[OFF_WOF + ((nt * 4 + kh) * 32 + lane) * 2 + 1];
                #pragma unroll
                for (int mt2 = 0; mt2 < 2; ++mt2)
                    mma_f16(co[mt2], Ah[mt2][kh], b0, b1);
            }
            const int col0 = nt * 8 + 2 * qcol;
            float bo0 = sm[OFF_BO + col0], bo1 = sm[OFF_BO + col0 + 1];
            #pragma unroll
            for (int mt2 = 0; mt2 < 2; ++mt2) {
                int row = r0 + (mh * 2 + mt2) * 16 + qrow;
                *(float2*)&outs[row * 64 + col0]       = make_float2(co[mt2][0] + bo0, co[mt2][1] + bo1);
                *(float2*)&outs[(row + 8) * 64 + col0] = make_float2(co[mt2][2] + bo0, co[mt2][3] + bo1);
            }
        }
    }
}

extern "C" void kernel_launch(void* const* d_in, const int* in_sizes, int n_in,
                              void* d_out, int out_size) {
    (void)in_sizes; (void)n_in; (void)out_size;
    const float* m    = (const float*)d_in[0];
    const float* mask = (const float*)d_in[1];
    const float* Wq   = (const float*)d_in[2];
    const float* Wk   = (const float*)d_in[3];
    const float* Wv   = (const float*)d_in[4];
    const float* Wg   = (const float*)d_in[5];
    const float* bg   = (const float*)d_in[6];
    const float* Wo   = (const float*)d_in[7];
    const float* bo   = (const float*)d_in[8];
    float* out = (float*)d_out;

    cudaFuncSetAttribute(ga_kernel, cudaFuncAttributeMaxDynamicSharedMemorySize, SMEM_BYTES);
    ga_kernel<<<SS, NT, SMEM_BYTES>>>(m, mask, Wq, Wk, Wv, Wg, bg, Wo, bo, out);
}

// round 9
// speedup vs baseline: 1.3488x; 1.3488x over previous
#include <cuda_runtime.h>
#include <cuda_fp16.h>
#include <math.h>
#include <stdint.h>

#define SS 2048
#define RR 512
#define NT 256
#define MHW 36    // m row stride in words (72 halves); 36 % 32 == 4 -> frag gather conflict-free

// ---- shared memory layout (32-bit word offsets) ----
static constexpr int OFF_M    = 0;                    // fp16 m: 512*36 = 18432
static constexpr int OFF_WGF  = 18432;                // Wg B-frags 2048
static constexpr int OFF_WOF  = OFF_WGF + 2048;       // Wo frags 2048
static constexpr int OFF_WKF  = OFF_WOF + 2048;       // Wk frags 256
static constexpr int OFF_WVF  = OFF_WKF + 256;        // Wv frags 256
static constexpr int OFF_KV   = OFF_WVF + 256;        // 512 rows * 9: K(4xh2) V(4xh2) bias(f32)
static constexpr int OFF_PART = OFF_KV + RR * 9;      // 8 warps * 64
static constexpr int OFF_POOL = OFF_PART + 512;       // 64 scratch (redundant identical writes)
static constexpr int OFF_QH   = OFF_POOL + 64;        // 64
static constexpr int OFF_OF   = OFF_QH + 64;          // 64
static constexpr int OFF_BG   = OFF_OF + 64;
static constexpr int OFF_BO   = OFF_BG + 64;
static constexpr int SMEM_WORDS = OFF_BO + 64;        // 28480
static constexpr int SMEM_BYTES = SMEM_WORDS * 4;     // 113920 B -> 2 CTAs/SM (229888 w/ 1KB resv)

__device__ __forceinline__ uint32_t packh2(float lo, float hi) {
    __half2 h = __floats2half2_rn(lo, hi);
    return *(uint32_t*)&h;
}
__device__ __forceinline__ float2 h2f2(uint32_t u) {
    return __half22float2(*(__half2*)&u);
}
__device__ __forceinline__ void mma_f16(float c[4], const uint32_t a[4],
                                        uint32_t b0, uint32_t b1)
{
    asm("mma.sync.aligned.m16n8k16.row.col.f32.f16.f16.f32 "
        "{%0,%1,%2,%3}, {%4,%5,%6,%7}, {%8,%9}, {%0,%1,%2,%3};"
        : "+f"(c[0]), "+f"(c[1]), "+f"(c[2]), "+f"(c[3])
        : "r"(a[0]), "r"(a[1]), "r"(a[2]), "r"(a[3]), "r"(b0), "r"(b1));
}

__global__ void __launch_bounds__(NT, 2) ga_kernel(
    const float* __restrict__ m, const float* __restrict__ mask,
    const float* __restrict__ Wq, const float* __restrict__ Wk,
    const float* __restrict__ Wv, const float* __restrict__ Wg,
    const float* __restrict__ bg, const float* __restrict__ Wo,
    const float* __restrict__ bo, float* __restrict__ out)
{
    extern __shared__ float sm[];
    uint32_t* smu = (uint32_t*)sm;
    const int s    = blockIdx.x;
    const int tid  = threadIdx.x;
    const int warp = tid >> 5, lane = tid & 31;
    const int qrow = lane >> 2, qcol = lane & 3;
    const float* m_s    = m + (size_t)s * (RR * 64);
    const float* mask_g = mask + (size_t)s * RR;

    // ---------- Phase 0: stage m fp16 + pool partials + bias + weight frags ----------
    {
        const float4* m4 = (const float4*)m_s;
        const int cg4 = tid & 15, rbase = tid >> 4;
        float px = 0.f, py = 0.f, pz = 0.f, pw = 0.f;
        #pragma unroll
        for (int j = 0; j < 32; ++j) {
            int r = rbase + j * 16;
            float4 v = m4[r * 16 + cg4];
            float mk = __ldg(mask_g + r);
            px += v.x * mk; py += v.y * mk; pz += v.z * mk; pw += v.w * mk;
            smu[OFF_M + r * MHW + cg4 * 2]     = packh2(v.x, v.y);
            smu[OFF_M + r * MHW + cg4 * 2 + 1] = packh2(v.z, v.w);
        }
        px += __shfl_down_sync(0xFFFFFFFFu, px, 16);
        py += __shfl_down_sync(0xFFFFFFFFu, py, 16);
        pz += __shfl_down_sync(0xFFFFFFFFu, pz, 16);
        pw += __shfl_down_sync(0xFFFFFFFFu, pw, 16);
        if (lane < 16) {
            float4 pp; pp.x = px; pp.y = py; pp.z = pz; pp.w = pw;
            *(float4*)&sm[OFF_PART + warp * 64 + cg4 * 4] = pp;
        }
        #pragma unroll
        for (int i = tid; i < RR; i += NT)
            sm[OFF_KV + i * 9 + 8] = 1e9f * (__ldg(mask_g + i) - 1.0f);   // softmax bias
        if (tid < 64) { sm[OFF_BG + tid] = bg[tid]; sm[OFF_BO + tid] = bo[tid]; }

        // B-fragments (m16n8k16.row.col): b0={W[k0][n],W[k0+1][n]}, b1={W[k0+8][n],W[k0+9][n]},
        // k0 = ktg*16 + 2*qcol, n = nt*8 + qrow
        #pragma unroll
        for (int it = 0; it < 4; ++it) {
            int idx = it * 8 + warp;          // 0..31 -> (nt, ktg)
            int nt = idx >> 2, ktg = idx & 3;
            int d0 = ktg * 16 + 2 * qcol;
            int cc = nt * 8 + qrow;
            int off = ((nt * 4 + ktg) * 32 + lane) * 2;
            smu[OFF_WGF + off]     = packh2(Wg[d0 * 64 + cc],       Wg[(d0 + 1) * 64 + cc]);
            smu[OFF_WGF + off + 1] = packh2(Wg[(d0 + 8) * 64 + cc], Wg[(d0 + 9) * 64 + cc]);
            smu[OFF_WOF + off]     = packh2(Wo[d0 * 64 + cc],       Wo[(d0 + 1) * 64 + cc]);
            smu[OFF_WOF + off + 1] = packh2(Wo[(d0 + 8) * 64 + cc], Wo[(d0 + 9) * 64 + cc]);
        }
        if (warp < 4) {
            int ktg = warp;
            int d0 = ktg * 16 + 2 * qcol;
            int off = (ktg * 32 + lane) * 2;
            smu[OFF_WKF + off]     = packh2(Wk[d0 * 8 + qrow],       Wk[(d0 + 1) * 8 + qrow]);
            smu[OFF_WKF + off + 1] = packh2(Wk[(d0 + 8) * 8 + qrow], Wk[(d0 + 9) * 8 + qrow]);
            smu[OFF_WVF + off]     = packh2(Wv[d0 * 8 + qrow],       Wv[(d0 + 1) * 8 + qrow]);
            smu[OFF_WVF + off + 1] = packh2(Wv[(d0 + 8) * 8 + qrow], Wv[(d0 + 9) * 8 + qrow]);
        }
    }
    __syncthreads();   // B1: m, PART, frags, bias ready

    // ================= each warp owns 64 rows r0..r0+63; warp = head =================
    const int r0 = warp * 64;

    // ---------- Phase 1: per-warp pool + q (redundant across warps; PART ready) ----------
    float qv[8];
    {
        float p0 = 0.f, p1 = 0.f;
        #pragma unroll
        for (int w = 0; w < 8; ++w) {
            p0 += sm[OFF_PART + w * 64 + lane];
            p1 += sm[OFF_PART + w * 64 + lane + 32];
        }
        sm[OFF_POOL + lane]      = p0;   // all warps write identical values (benign)
        sm[OFF_POOL + lane + 32] = p1;
        float ms = 0.f;
        #pragma unroll
        for (int j = 0; j < 16; ++j) ms += __ldg(mask_g + lane + 32 * j);   // L1/L2-hot
        #pragma unroll
        for (int o = 16; o; o >>= 1) ms += __shfl_xor_sync(0xFFFFFFFFu, ms, o);
        __syncwarp();
        const int c = lane & 7, qr = lane >> 3;   // lane -> (col, d-quarter)
        float acc = 0.f;
        #pragma unroll
        for (int dd = 0; dd < 16; ++dd) {
            int d = qr * 16 + dd;
            acc += sm[OFF_POOL + d] * __ldg(&Wq[d * 64 + warp * 8 + c]);
        }
        acc += __shfl_xor_sync(0xFFFFFFFFu, acc, 8);
        acc += __shfl_xor_sync(0xFFFFFFFFu, acc, 16);
        float qs = 0.35355339059327373f / (ms + 1e-10f);
        if (lane < 8) sm[OFF_QH + warp * 8 + lane] = acc * qs;
        __syncwarp();
        #pragma unroll
        for (int cc = 0; cc < 8; ++cc) qv[cc] = sm[OFF_QH + warp * 8 + cc];
    }

    // ---------- Phase 2: k = m@Wk, v = m@Wv via mma (A-frags from smem) ----------
    {
        uint32_t Af[4][4][4];
        #pragma unroll
        for (int mt = 0; mt < 4; ++mt)
            #pragma unroll
            for (int ktg = 0; ktg < 4; ++ktg) {
                int w = OFF_M + (r0 + mt * 16 + qrow) * MHW + ktg * 8 + qcol;
                Af[mt][ktg][0] = smu[w];
                Af[mt][ktg][1] = smu[w + 8 * MHW];
                Af[mt][ktg][2] = smu[w + 4];
                Af[mt][ktg][3] = smu[w + 8 * MHW + 4];
            }
        uint32_t b[4][2];
        #pragma unroll
        for (int ktg = 0; ktg < 4; ++ktg) {
            b[ktg][0] = smu[OFF_WKF + (ktg * 32 + lane) * 2];
            b[ktg][1] = smu[OFF_WKF + (ktg * 32 + lane) * 2 + 1];
        }
        float ck[4][4] = {{0,0,0,0},{0,0,0,0},{0,0,0,0},{0,0,0,0}};
        #pragma unroll
        for (int ktg = 0; ktg < 4; ++ktg)
            #pragma unroll
            for (int mt = 0; mt < 4; ++mt)
                mma_f16(ck[mt], Af[mt][ktg], b[ktg][0], b[ktg][1]);
        #pragma unroll
        for (int mt = 0; mt < 4; ++mt) {
            int row = r0 + mt * 16 + qrow;
            smu[OFF_KV + row * 9 + qcol]       = packh2(ck[mt][0], ck[mt][1]);
            smu[OFF_KV + (row + 8) * 9 + qcol] = packh2(ck[mt][2], ck[mt][3]);
        }
        #pragma unroll
        for (int ktg = 0; ktg < 4; ++ktg) {
            b[ktg][0] = smu[OFF_WVF + (ktg * 32 + lane) * 2];
            b[ktg][1] = smu[OFF_WVF + (ktg * 32 + lane) * 2 + 1];
        }
        float cv[4][4] = {{0,0,0,0},{0,0,0,0},{0,0,0,0},{0,0,0,0}};
        #pragma unroll
        for (int ktg = 0; ktg < 4; ++ktg)
            #pragma unroll
            for (int mt = 0; mt < 4; ++mt)
                mma_f16(cv[mt], Af[mt][ktg], b[ktg][0], b[ktg][1]);
        #pragma unroll
        for (int mt = 0; mt < 4; ++mt) {
            int row = r0 + mt * 16 + qrow;
            smu[OFF_KV + row * 9 + 4 + qcol]       = packh2(cv[mt][0], cv[mt][1]);
            smu[OFF_KV + (row + 8) * 9 + 4 + qcol] = packh2(cv[mt][2], cv[mt][3]);
        }
    }
    __syncthreads();   // B2: KV ready

    // ---------- Phase 3: attention (warp = head; bias -1e9 kills masked rows) ----------
    {
        float sum = 0.f;
        float oa[8] = {0,0,0,0,0,0,0,0};
        #pragma unroll
        for (int i = 0; i < 16; ++i) {
            int r = i * 32 + lane;
            const uint32_t* kv = smu + OFF_KV + r * 9;
            float2 k0 = h2f2(kv[0]), k1 = h2f2(kv[1]), k2 = h2f2(kv[2]), k3 = h2f2(kv[3]);
            float bias = sm[OFF_KV + r * 9 + 8];
            float a = qv[0]*k0.x + qv[1]*k0.y + qv[2]*k1.x + qv[3]*k1.y
                    + qv[4]*k2.x + qv[5]*k2.y + qv[6]*k3.x + qv[7]*k3.y + bias;
            float p = __expf(a);
            sum += p;
            float2 v0 = h2f2(kv[4]), v1 = h2f2(kv[5]), v2 = h2f2(kv[6]), v3 = h2f2(kv[7]);
            oa[0] += p * v0.x; oa[1] += p * v0.y; oa[2] += p * v1.x; oa[3] += p * v1.y;
            oa[4] += p * v2.x; oa[5] += p * v2.y; oa[6] += p * v3.x; oa[7] += p * v3.y;
        }
        #pragma unroll
        for (int o = 16; o; o >>= 1) sum += __shfl_xor_sync(0xFFFFFFFFu, sum, o);
        #pragma unroll
        for (int c = 0; c < 8; ++c) {
            #pragma unroll
            for (int o = 16; o; o >>= 1) oa[c] += __shfl_xor_sync(0xFFFFFFFFu, oa[c], o);
        }
        if (lane == 0) {
            float inv = 1.f / sum;
            #pragma unroll
            for (int c = 0; c < 8; ++c) sm[OFF_OF + warp * 8 + c] = oa[c] * inv;
        }
    }
    __syncthreads();   // B3: OF ready for all warps

    // ---------- Phase 4: gate + output GEMM; h register-resident (acc -> A-frag identity) ----------
    float* outs = out + (size_t)s * (RR * 64);
    #pragma unroll
    for (int mh = 0; mh < 2; ++mh) {
        uint32_t Am[2][4][4];
        #pragma unroll
        for (int mt2 = 0; mt2 < 2; ++mt2)
            #pragma unroll
            for (int ktg = 0; ktg < 4; ++ktg) {
                int w = OFF_M + (r0 + (mh * 2 + mt2) * 16 + qrow) * MHW + ktg * 8 + qcol;
                Am[mt2][ktg][0] = smu[w];
                Am[mt2][ktg][1] = smu[w + 8 * MHW];
                Am[mt2][ktg][2] = smu[w + 4];
                Am[mt2][ktg][3] = smu[w + 8 * MHW + 4];
            }

        uint32_t Ah[2][4][4];
        #pragma unroll
        for (int kh = 0; kh < 4; ++kh) {
            #pragma unroll
            for (int sub = 0; sub < 2; ++sub) {
                const int nt = 2 * kh + sub;
                float cg[2][4] = {{0,0,0,0},{0,0,0,0}};
                #pragma unroll
                for (int ktg = 0; ktg < 4; ++ktg) {
                    uint32_t b0 = smu[OFF_WGF + ((nt * 4 + ktg) * 32 + lane) * 2];
                    uint32_t b1 = smu[OFF_WGF + ((nt * 4 + ktg) * 32 + lane) * 2 + 1];
                    #pragma unroll
                    for (int mt2 = 0; mt2 < 2; ++mt2)
                        mma_f16(cg[mt2], Am[mt2][ktg], b0, b1);
                }
                const int col0 = nt * 8 + 2 * qcol;
                float of0 = sm[OFF_OF + col0], of1 = sm[OFF_OF + col0 + 1];
                float bg0 = sm[OFF_BG + col0], bg1 = sm[OFF_BG + col0 + 1];
                #pragma unroll
                for (int mt2 = 0; mt2 < 2; ++mt2) {
                    float h0 = of0 / (1.f + __expf(-(cg[mt2][0] + bg0)));
                    float h1 = of1 / (1.f + __expf(-(cg[mt2][1] + bg1)));
                    float h2 = of0 / (1.f + __expf(-(cg[mt2][2] + bg0)));
                    float h3 = of1 / (1.f + __expf(-(cg[mt2][3] + bg1)));
                    Ah[mt2][kh][sub * 2]     = packh2(h0, h1);
                    Ah[mt2][kh][sub * 2 + 1] = packh2(h2, h3);
                }
            }
        }
        #pragma unroll
        for (int nt = 0; nt < 8; ++nt) {
            float co[2][4] = {{0,0,0,0},{0,0,0,0}};
            #pragma unroll
            for (int kh = 0; kh < 4; ++kh) {
                uint32_t b0 = smu[OFF_WOF + ((nt * 4 + kh) * 32 + lane) * 2];
                uint32_t b1 = smu[OFF_WOF + ((nt * 4 + kh) * 32 + lane) * 2 + 1];
                #pragma unroll
                for (int mt2 = 0; mt2 < 2; ++mt2)
                    mma_f16(co[mt2], Ah[mt2][kh], b0, b1);
            }
            const int col0 = nt * 8 + 2 * qcol;
            float bo0 = sm[OFF_BO + col0], bo1 = sm[OFF_BO + col0 + 1];
            #pragma unroll
            for (int mt2 = 0; mt2 < 2; ++mt2) {
                int row = r0 + (mh * 2 + mt2) * 16 + qrow;
                *(float2*)&outs[row * 64 + col0]       = make_float2(co[mt2][0] + bo0, co[mt2][1] + bo1);
                *(float2*)&outs[(row + 8) * 64 + col0] = make_float2(co[mt2][2] + bo0, co[mt2][3] + bo1);
            }
        }
    }
}

extern "C" void kernel_launch(void* const* d_in, const int* in_sizes, int n_in,
                              void* d_out, int out_size) {
    (void)in_sizes; (void)n_in; (void)out_size;
    const float* m    = (const float*)d_in[0];
    const float* mask = (const float*)d_in[1];
    const float* Wq   = (const float*)d_in[2];
    const float* Wk   = (const float*)d_in[3];
    const float* Wv   = (const float*)d_in[4];
    const float* Wg   = (const float*)d_in[5];
    const float* bg   = (const float*)d_in[6];
    const float* Wo   = (const float*)d_in[7];
    const float* bo   = (const float*)d_in[8];
    float* out = (float*)d_out;

    cudaFuncSetAttribute(ga_kernel, cudaFuncAttributeMaxDynamicSharedMemorySize, SMEM_BYTES);
    ga_kernel<<<SS, NT, SMEM_BYTES>>>(m, mask, Wq, Wk, Wv, Wg, bg, Wo, bo, out);
}

// round 10
// speedup vs baseline: 1.3531x; 1.0032x over previous
#include <cuda_runtime.h>
#include <cuda_fp16.h>
#include <math.h>
#include <stdint.h>

#define SS 2048
#define RR 512
#define NT 256
#define MHW 36    // m row stride in words (72 halves); 36 % 32 == 4 -> frag gather conflict-free

// ---- shared memory layout (32-bit word offsets) ----
static constexpr int OFF_M    = 0;                    // fp16 m (frag layout): 512*36 = 18432
static constexpr int OFF_WGF  = 18432;                // Wg B-frags 2048
static constexpr int OFF_WOF  = OFF_WGF + 2048;       // Wo frags 2048
static constexpr int OFF_KV   = OFF_WOF + 2048;       // 512 rows * 9: K(4xh2) V(4xh2) bias(f32)
static constexpr int OFF_PART = OFF_KV + RR * 9;      // 8 warps * 64
static constexpr int OFF_POOL = OFF_PART + 512;       // 64 (redundant identical writes)
static constexpr int OFF_QH   = OFF_POOL + 64;        // 64
static constexpr int OFF_OF   = OFF_QH + 64;          // 64
static constexpr int OFF_BG   = OFF_OF + 64;
static constexpr int OFF_BO   = OFF_BG + 64;
static constexpr int OFF_MS   = OFF_BO + 64;          // 4
static constexpr int SMEM_WORDS = OFF_MS + 4;         // 27972
static constexpr int SMEM_BYTES = SMEM_WORDS * 4;     // 111888 B -> 2 CTAs/SM

__device__ __forceinline__ uint32_t packh2(float lo, float hi) {
    __half2 h = __floats2half2_rn(lo, hi);
    return *(uint32_t*)&h;
}
__device__ __forceinline__ float2 h2f2(uint32_t u) {
    return __half22float2(*(__half2*)&u);
}
__device__ __forceinline__ float tanh_fast(float x) {
    float y; asm("tanh.approx.f32 %0, %1;" : "=f"(y) : "f"(x)); return y;
}
__device__ __forceinline__ void mma_f16(float c[4], const uint32_t a[4],
                                        uint32_t b0, uint32_t b1)
{
    asm("mma.sync.aligned.m16n8k16.row.col.f32.f16.f16.f32 "
        "{%0,%1,%2,%3}, {%4,%5,%6,%7}, {%8,%9}, {%0,%1,%2,%3};"
        : "+f"(c[0]), "+f"(c[1]), "+f"(c[2]), "+f"(c[3])
        : "r"(a[0]), "r"(a[1]), "r"(a[2]), "r"(a[3]), "r"(b0), "r"(b1));
}

__global__ void __launch_bounds__(NT, 2) ga_kernel(
    const float* __restrict__ m, const float* __restrict__ mask,
    const float* __restrict__ Wq, const float* __restrict__ Wk,
    const float* __restrict__ Wv, const float* __restrict__ Wg,
    const float* __restrict__ bg, const float* __restrict__ Wo,
    const float* __restrict__ bo, float* __restrict__ out)
{
    extern __shared__ float sm[];
    uint32_t* smu = (uint32_t*)sm;
    const int s    = blockIdx.x;
    const int tid  = threadIdx.x;
    const int warp = tid >> 5, lane = tid & 31;
    const int qrow = lane >> 2, qcol = lane & 3;
    const float* m_s    = m + (size_t)s * (RR * 64);
    const float* mask_g = mask + (size_t)s * RR;
    const int r0 = warp * 64;   // each warp owns 64 rows; warp = head

    // ---------- Phase 0 (no barrier needed after): weights, bias, ms; k/v B-frags in regs ----------
    uint32_t bk[4][2], bv[4][2];
    {
        // Wg/Wo B-fragments into smem (m16n8k16.row.col):
        // b0={W[k0][n],W[k0+1][n]}, b1={W[k0+8][n],W[k0+9][n]}, k0=ktg*16+2*qcol, n=nt*8+qrow
        #pragma unroll
        for (int it = 0; it < 4; ++it) {
            int idx = it * 8 + warp;          // 0..31 -> (nt, ktg)
            int nt = idx >> 2, ktg = idx & 3;
            int d0 = ktg * 16 + 2 * qcol;
            int cc = nt * 8 + qrow;
            int off = ((nt * 4 + ktg) * 32 + lane) * 2;
            smu[OFF_WGF + off]     = packh2(Wg[d0 * 64 + cc],       Wg[(d0 + 1) * 64 + cc]);
            smu[OFF_WGF + off + 1] = packh2(Wg[(d0 + 8) * 64 + cc], Wg[(d0 + 9) * 64 + cc]);
            smu[OFF_WOF + off]     = packh2(Wo[d0 * 64 + cc],       Wo[(d0 + 1) * 64 + cc]);
            smu[OFF_WOF + off + 1] = packh2(Wo[(d0 + 8) * 64 + cc], Wo[(d0 + 9) * 64 + cc]);
        }
        // per-warp K/V B-frags straight to registers (2 KB tables, L1-hot)
        #pragma unroll
        for (int ktg = 0; ktg < 4; ++ktg) {
            int d0 = ktg * 16 + 2 * qcol;
            bk[ktg][0] = packh2(__ldg(Wk + d0 * 8 + qrow),       __ldg(Wk + (d0 + 1) * 8 + qrow));
            bk[ktg][1] = packh2(__ldg(Wk + (d0 + 8) * 8 + qrow), __ldg(Wk + (d0 + 9) * 8 + qrow));
            bv[ktg][0] = packh2(__ldg(Wv + d0 * 8 + qrow),       __ldg(Wv + (d0 + 1) * 8 + qrow));
            bv[ktg][1] = packh2(__ldg(Wv + (d0 + 8) * 8 + qrow), __ldg(Wv + (d0 + 9) * 8 + qrow));
        }
        #pragma unroll
        for (int i = tid; i < RR; i += NT)
            sm[OFF_KV + i * 9 + 8] = 1e9f * (__ldg(mask_g + i) - 1.0f);   // softmax bias
        if (tid < 64) { sm[OFF_BG + tid] = bg[tid]; sm[OFF_BO + tid] = bo[tid]; }
        if (warp == 0) {
            float ms = 0.f;
            #pragma unroll
            for (int j = 0; j < 16; ++j) ms += __ldg(mask_g + lane + 32 * j);
            #pragma unroll
            for (int o = 16; o; o >>= 1) ms += __shfl_xor_sync(0xFFFFFFFFu, ms, o);
            if (lane == 0) sm[OFF_MS] = ms;
        }
    }

    // ---------- Phase 1: fused m load (gmem, frag order) + pool fold + k/v mma + m->smem ----------
    {
        float mk0[4], mk1[4];
        #pragma unroll
        for (int mt = 0; mt < 4; ++mt) {
            mk0[mt] = __ldg(mask_g + r0 + mt * 16 + qrow);
            mk1[mt] = __ldg(mask_g + r0 + mt * 16 + qrow + 8);
        }
        float2 pc[4][2];
        #pragma unroll
        for (int k = 0; k < 4; ++k) { pc[k][0] = make_float2(0.f, 0.f); pc[k][1] = make_float2(0.f, 0.f); }
        float ck[4][4] = {{0,0,0,0},{0,0,0,0},{0,0,0,0},{0,0,0,0}};
        float cv[4][4] = {{0,0,0,0},{0,0,0,0},{0,0,0,0},{0,0,0,0}};

        #pragma unroll
        for (int ktg = 0; ktg < 4; ++ktg) {
            uint32_t A[4][4];
            #pragma unroll
            for (int mt = 0; mt < 4; ++mt) {
                const float* base = m_s + (r0 + mt * 16 + qrow) * 64 + ktg * 16 + 2 * qcol;
                float2 f0 = *(const float2*)base;            // (row,   k..k+1)
                float2 f1 = *(const float2*)(base + 8 * 64); // (row+8, k..k+1)
                float2 f2 = *(const float2*)(base + 8);      // (row,   k+8..k+9)
                float2 f3 = *(const float2*)(base + 8 * 64 + 8);
                A[mt][0] = packh2(f0.x, f0.y);
                A[mt][1] = packh2(f1.x, f1.y);
                A[mt][2] = packh2(f2.x, f2.y);
                A[mt][3] = packh2(f3.x, f3.y);
                pc[ktg][0].x += f0.x * mk0[mt] + f1.x * mk1[mt];
                pc[ktg][0].y += f0.y * mk0[mt] + f1.y * mk1[mt];
                pc[ktg][1].x += f2.x * mk0[mt] + f3.x * mk1[mt];
                pc[ktg][1].y += f2.y * mk0[mt] + f3.y * mk1[mt];
                // persist m as fp16 in frag-gather layout for phase 4
                int w = OFF_M + (r0 + mt * 16 + qrow) * MHW + ktg * 8 + qcol;
                smu[w]               = A[mt][0];
                smu[w + 8 * MHW]     = A[mt][1];
                smu[w + 4]           = A[mt][2];
                smu[w + 8 * MHW + 4] = A[mt][3];
            }
            #pragma unroll
            for (int mt = 0; mt < 4; ++mt) {
                mma_f16(ck[mt], A[mt], bk[ktg][0], bk[ktg][1]);
                mma_f16(cv[mt], A[mt], bv[ktg][0], bv[ktg][1]);
            }
        }
        // KV store (fp16 interleaved, stride 9 words)
        #pragma unroll
        for (int mt = 0; mt < 4; ++mt) {
            int row = r0 + mt * 16 + qrow;
            smu[OFF_KV + row * 9 + qcol]           = packh2(ck[mt][0], ck[mt][1]);
            smu[OFF_KV + (row + 8) * 9 + qcol]     = packh2(ck[mt][2], ck[mt][3]);
            smu[OFF_KV + row * 9 + 4 + qcol]       = packh2(cv[mt][0], cv[mt][1]);
            smu[OFF_KV + (row + 8) * 9 + 4 + qcol] = packh2(cv[mt][2], cv[mt][3]);
        }
        // pool partial reduce over qrow (lanes sharing qcol): xor 4, 8, 16
        #pragma unroll
        for (int k = 0; k < 4; ++k)
            #pragma unroll
            for (int p = 0; p < 2; ++p) {
                #pragma unroll
                for (int o = 4; o <= 16; o <<= 1) {
                    pc[k][p].x += __shfl_xor_sync(0xFFFFFFFFu, pc[k][p].x, o);
                    pc[k][p].y += __shfl_xor_sync(0xFFFFFFFFu, pc[k][p].y, o);
                }
            }
        if (lane < 4) {   // qrow == 0 holds the reduced values
            #pragma unroll
            for (int k = 0; k < 4; ++k) {
                *(float2*)&sm[OFF_PART + warp * 64 + k * 16 + 2 * qcol]     = pc[k][0];
                *(float2*)&sm[OFF_PART + warp * 64 + k * 16 + 8 + 2 * qcol] = pc[k][1];
            }
        }
    }
    __syncthreads();   // B2: KV, PART, bias, Wg/Wo frags, ms all ready

    // ---------- Phase 2: per-warp pool + q (redundant across warps) ----------
    float qv[8];
    {
        float p0 = 0.f, p1 = 0.f;
        #pragma unroll
        for (int w = 0; w < 8; ++w) {
            p0 += sm[OFF_PART + w * 64 + lane];
            p1 += sm[OFF_PART + w * 64 + lane + 32];
        }
        sm[OFF_POOL + lane]      = p0;   // all warps write identical values (benign)
        sm[OFF_POOL + lane + 32] = p1;
        float ms = sm[OFF_MS];
        __syncwarp();
        const int c = lane & 7, qr = lane >> 3;   // lane -> (col, d-quarter)
        float acc = 0.f;
        #pragma unroll
        for (int dd = 0; dd < 16; ++dd) {
            int d = qr * 16 + dd;
            acc += sm[OFF_POOL + d] * __ldg(&Wq[d * 64 + warp * 8 + c]);
        }
        acc += __shfl_xor_sync(0xFFFFFFFFu, acc, 8);
        acc += __shfl_xor_sync(0xFFFFFFFFu, acc, 16);
        float qs = 0.35355339059327373f / (ms + 1e-10f);
        if (lane < 8) sm[OFF_QH + warp * 8 + lane] = acc * qs;
        __syncwarp();
        #pragma unroll
        for (int cc = 0; cc < 8; ++cc) qv[cc] = sm[OFF_QH + warp * 8 + cc];
    }

    // ---------- Phase 3: attention (warp = head; bias -1e9 kills masked rows) ----------
    {
        float sum = 0.f;
        float oa[8] = {0,0,0,0,0,0,0,0};
        #pragma unroll
        for (int i = 0; i < 16; ++i) {
            int r = i * 32 + lane;
            const uint32_t* kv = smu + OFF_KV + r * 9;
            float2 k0 = h2f2(kv[0]), k1 = h2f2(kv[1]), k2 = h2f2(kv[2]), k3 = h2f2(kv[3]);
            float bias = sm[OFF_KV + r * 9 + 8];
            float a = qv[0]*k0.x + qv[1]*k0.y + qv[2]*k1.x + qv[3]*k1.y
                    + qv[4]*k2.x + qv[5]*k2.y + qv[6]*k3.x + qv[7]*k3.y + bias;
            float p = __expf(a);
            sum += p;
            float2 v0 = h2f2(kv[4]), v1 = h2f2(kv[5]), v2 = h2f2(kv[6]), v3 = h2f2(kv[7]);
            oa[0] += p * v0.x; oa[1] += p * v0.y; oa[2] += p * v1.x; oa[3] += p * v1.y;
            oa[4] += p * v2.x; oa[5] += p * v2.y; oa[6] += p * v3.x; oa[7] += p * v3.y;
        }
        #pragma unroll
        for (int o = 16; o; o >>= 1) sum += __shfl_xor_sync(0xFFFFFFFFu, sum, o);
        #pragma unroll
        for (int c = 0; c < 8; ++c) {
            #pragma unroll
            for (int o = 16; o; o >>= 1) oa[c] += __shfl_xor_sync(0xFFFFFFFFu, oa[c], o);
        }
        if (lane == 0) {
            float inv = 1.f / sum;
            #pragma unroll
            for (int c = 0; c < 8; ++c) sm[OFF_OF + warp * 8 + c] = oa[c] * inv;
        }
    }
    __syncthreads();   // B3: OF ready for all warps

    // ---------- Phase 4: gate + output GEMM; h register-resident (acc -> A-frag identity) ----------
    // sigmoid via tanh.approx: of*sig(x) = fma(hof, tanh(0.5x + hbg), hof)
    float* outs = out + (size_t)s * (RR * 64);
    #pragma unroll
    for (int mh = 0; mh < 2; ++mh) {
        uint32_t Am[2][4][4];
        #pragma unroll
        for (int mt2 = 0; mt2 < 2; ++mt2)
            #pragma unroll
            for (int ktg = 0; ktg < 4; ++ktg) {
                int w = OFF_M + (r0 + (mh * 2 + mt2) * 16 + qrow) * MHW + ktg * 8 + qcol;
                Am[mt2][ktg][0] = smu[w];
                Am[mt2][ktg][1] = smu[w + 8 * MHW];
                Am[mt2][ktg][2] = smu[w + 4];
                Am[mt2][ktg][3] = smu[w + 8 * MHW + 4];
            }

        uint32_t Ah[2][4][4];
        #pragma unroll
        for (int kh = 0; kh < 4; ++kh) {
            #pragma unroll
            for (int sub = 0; sub < 2; ++sub) {
                const int nt = 2 * kh + sub;
                float cg[2][4] = {{0,0,0,0},{0,0,0,0}};
                #pragma unroll
                for (int ktg = 0; ktg < 4; ++ktg) {
                    uint32_t b0 = smu[OFF_WGF + ((nt * 4 + ktg) * 32 + lane) * 2];
                    uint32_t b1 = smu[OFF_WGF + ((nt * 4 + ktg) * 32 + lane) * 2 + 1];
                    #pragma unroll
                    for (int mt2 = 0; mt2 < 2; ++mt2)
                        mma_f16(cg[mt2], Am[mt2][ktg], b0, b1);
                }
                const int col0 = nt * 8 + 2 * qcol;
                float hof0 = 0.5f * sm[OFF_OF + col0], hof1 = 0.5f * sm[OFF_OF + col0 + 1];
                float hbg0 = 0.5f * sm[OFF_BG + col0], hbg1 = 0.5f * sm[OFF_BG + col0 + 1];
                #pragma unroll
                for (int mt2 = 0; mt2 < 2; ++mt2) {
                    float h0 = fmaf(hof0, tanh_fast(fmaf(0.5f, cg[mt2][0], hbg0)), hof0);
                    float h1 = fmaf(hof1, tanh_fast(fmaf(0.5f, cg[mt2][1], hbg1)), hof1);
                    float h2 = fmaf(hof0, tanh_fast(fmaf(0.5f, cg[mt2][2], hbg0)), hof0);
                    float h3 = fmaf(hof1, tanh_fast(fmaf(0.5f, cg[mt2][3], hbg1)), hof1);
                    Ah[mt2][kh][sub * 2]     = packh2(h0, h1);
                    Ah[mt2][kh][sub * 2 + 1] = packh2(h2, h3);
                }
            }
        }
        #pragma unroll
        for (int nt = 0; nt < 8; ++nt) {
            float co[2][4] = {{0,0,0,0},{0,0,0,0}};
            #pragma unroll
            for (int kh = 0; kh < 4; ++kh) {
                uint32_t b0 = smu[OFF_WOF + ((nt * 4 + kh) * 32 + lane) * 2];
                uint32_t b1 = smu[OFF_WOF + ((nt * 4 + kh) * 32 + lane) * 2 + 1];
                #pragma unroll
                for (int mt2 = 0; mt2 < 2; ++mt2)
                    mma_f16(co[mt2], Ah[mt2][kh], b0, b1);
            }
            const int col0 = nt * 8 + 2 * qcol;
            float bo0 = sm[OFF_BO + col0], bo1 = sm[OFF_BO + col0 + 1];
            #pragma unroll
            for (int mt2 = 0; mt2 < 2; ++mt2) {
                int row = r0 + (mh * 2 + mt2) * 16 + qrow;
                *(float2*)&outs[row * 64 + col0]       = make_float2(co[mt2][0] + bo0, co[mt2][1] + bo1);
                *(float2*)&outs[(row + 8) * 64 + col0] = make_float2(co[mt2][2] + bo0, co[mt2][3] + bo1);
            }
        }
    }
}

extern "C" void kernel_launch(void* const* d_in, const int* in_sizes, int n_in,
                              void* d_out, int out_size) {
    (void)in_sizes; (void)n_in; (void)out_size;
    const float* m    = (const float*)d_in[0];
    const float* mask = (const float*)d_in[1];
    const float* Wq   = (const float*)d_in[2];
    const float* Wk   = (const float*)d_in[3];
    const float* Wv   = (const float*)d_in[4];
    const float* Wg   = (const float*)d_in[5];
    const float* bg   = (const float*)d_in[6];
    const float* Wo   = (const float*)d_in[7];
    const float* bo   = (const float*)d_in[8];
    float* out = (float*)d_out;

    cudaFuncSetAttribute(ga_kernel, cudaFuncAttributeMaxDynamicSharedMemorySize, SMEM_BYTES);
    ga_kernel<<<SS, NT, SMEM_BYTES>>>(m, mask, Wq, Wk, Wv, Wg, bg, Wo, bo, out);
}

// round 11
// speedup vs baseline: 1.6759x; 1.2386x over previous
#include <cuda_runtime.h>
#include <cuda_fp16.h>
#include <math.h>
#include <stdint.h>

#define SS 2048
#define RR 512
#define NT 256

// ---- shared memory layout (32-bit word offsets) ----
static constexpr int OFF_WGF  = 0;                    // Wg B-frags 2048
static constexpr int OFF_WOF  = 2048;                 // Wo B-frags 2048
static constexpr int OFF_KV   = 4096;                 // 512 rows * 12 words: K(4xh2)@0-3, V(4xh2)@4-7, pad 8-11
static constexpr int OFF_BIAS = OFF_KV + RR * 12;     // 512 (softmax bias, flat: lane-indexed conflict-free)
static constexpr int OFF_PART = OFF_BIAS + 512;       // 8 warps * 64 pool partials
static constexpr int OFF_POOL = OFF_PART + 512;       // 64 (redundant identical writes)
static constexpr int OFF_QH   = OFF_POOL + 64;        // 64
static constexpr int OFF_OF   = OFF_QH + 64;          // 64
static constexpr int OFF_BG   = OFF_OF + 64;
static constexpr int OFF_BO   = OFF_BG + 64;
static constexpr int OFF_MS   = OFF_BO + 64;          // 4
static constexpr int SMEM_WORDS = OFF_MS + 4;         // 11588
static constexpr int SMEM_BYTES = SMEM_WORDS * 4;     // 46352 B -> 2 CTAs/SM easily

__device__ __forceinline__ uint32_t packh2(float lo, float hi) {
    __half2 h = __floats2half2_rn(lo, hi);
    return *(uint32_t*)&h;
}
__device__ __forceinline__ float2 h2f2(uint32_t u) {
    return __half22float2(*(__half2*)&u);
}
__device__ __forceinline__ float tanh_fast(float x) {
    float y; asm("tanh.approx.f32 %0, %1;" : "=f"(y) : "f"(x)); return y;
}
__device__ __forceinline__ void mma_f16(float c[4], const uint32_t a[4],
                                        uint32_t b0, uint32_t b1)
{
    asm("mma.sync.aligned.m16n8k16.row.col.f32.f16.f16.f32 "
        "{%0,%1,%2,%3}, {%4,%5,%6,%7}, {%8,%9}, {%0,%1,%2,%3};"
        : "+f"(c[0]), "+f"(c[1]), "+f"(c[2]), "+f"(c[3])
        : "r"(a[0]), "r"(a[1]), "r"(a[2]), "r"(a[3]), "r"(b0), "r"(b1));
}

__global__ void __launch_bounds__(NT, 2) ga_kernel(
    const float* __restrict__ m, const float* __restrict__ mask,
    const float* __restrict__ Wq, const float* __restrict__ Wk,
    const float* __restrict__ Wv, const float* __restrict__ Wg,
    const float* __restrict__ bg, const float* __restrict__ Wo,
    const float* __restrict__ bo, float* __restrict__ out)
{
    extern __shared__ float sm[];
    uint32_t* smu = (uint32_t*)sm;
    const int s    = blockIdx.x;
    const int tid  = threadIdx.x;
    const int warp = tid >> 5, lane = tid & 31;
    const int qrow = lane >> 2, qcol = lane & 3;
    const float* m_s    = m + (size_t)s * (RR * 64);
    const float* mask_g = mask + (size_t)s * RR;
    const int r0 = warp * 64;   // each warp owns 64 rows; warp = head

    // ---------- Phase 0: Wg/Wo frags to smem, bias array, BG/BO, mask sum ----------
    {
        // B-frags (m16n8k16.row.col): b0={W[k0][n],W[k0+1][n]}, b1={W[k0+8][n],W[k0+9][n]},
        // k0 = ktg*16 + 2*qcol, n = nt*8 + qrow
        #pragma unroll
        for (int it = 0; it < 4; ++it) {
            int idx = it * 8 + warp;          // 0..31 -> (nt, ktg)
            int nt = idx >> 2, ktg = idx & 3;
            int d0 = ktg * 16 + 2 * qcol;
            int cc = nt * 8 + qrow;
            int off = ((nt * 4 + ktg) * 32 + lane) * 2;
            smu[OFF_WGF + off]     = packh2(Wg[d0 * 64 + cc],       Wg[(d0 + 1) * 64 + cc]);
            smu[OFF_WGF + off + 1] = packh2(Wg[(d0 + 8) * 64 + cc], Wg[(d0 + 9) * 64 + cc]);
            smu[OFF_WOF + off]     = packh2(Wo[d0 * 64 + cc],       Wo[(d0 + 1) * 64 + cc]);
            smu[OFF_WOF + off + 1] = packh2(Wo[(d0 + 8) * 64 + cc], Wo[(d0 + 9) * 64 + cc]);
        }
        #pragma unroll
        for (int i = tid; i < RR; i += NT)
            sm[OFF_BIAS + i] = 1e9f * (__ldg(mask_g + i) - 1.0f);
        if (tid < 64) { sm[OFF_BG + tid] = bg[tid]; sm[OFF_BO + tid] = bo[tid]; }
        if (warp == 0) {
            float ms = 0.f;
            #pragma unroll
            for (int j = 0; j < 16; ++j) ms += __ldg(mask_g + lane + 32 * j);
            #pragma unroll
            for (int o = 16; o; o >>= 1) ms += __shfl_xor_sync(0xFFFFFFFFu, ms, o);
            if (lane == 0) sm[OFF_MS] = ms;
        }
    }

    // ---------- Phase 1: load m once (gmem, frag order) -> Af regs; fp32 pool; k/v mma ----------
    uint32_t Af[4][4][4];   // lives until end of kernel
    {
        float mk0[4], mk1[4];
        #pragma unroll
        for (int mt = 0; mt < 4; ++mt) {
            mk0[mt] = __ldg(mask_g + r0 + mt * 16 + qrow);
            mk1[mt] = __ldg(mask_g + r0 + mt * 16 + qrow + 8);
        }
        float2 pc[4][2];
        #pragma unroll
        for (int k = 0; k < 4; ++k) { pc[k][0] = make_float2(0.f, 0.f); pc[k][1] = make_float2(0.f, 0.f); }

        #pragma unroll
        for (int ktg = 0; ktg < 4; ++ktg)
            #pragma unroll
            for (int mt = 0; mt < 4; ++mt) {
                const float* base = m_s + (r0 + mt * 16 + qrow) * 64 + ktg * 16 + 2 * qcol;
                float2 f0 = *(const float2*)base;            // (row,   k..k+1)
                float2 f1 = *(const float2*)(base + 8 * 64); // (row+8, k..k+1)
                float2 f2 = *(const float2*)(base + 8);      // (row,   k+8..k+9)
                float2 f3 = *(const float2*)(base + 8 * 64 + 8);
                Af[mt][ktg][0] = packh2(f0.x, f0.y);
                Af[mt][ktg][1] = packh2(f1.x, f1.y);
                Af[mt][ktg][2] = packh2(f2.x, f2.y);
                Af[mt][ktg][3] = packh2(f3.x, f3.y);
                pc[ktg][0].x += f0.x * mk0[mt] + f1.x * mk1[mt];
                pc[ktg][0].y += f0.y * mk0[mt] + f1.y * mk1[mt];
                pc[ktg][1].x += f2.x * mk0[mt] + f3.x * mk1[mt];
                pc[ktg][1].y += f2.y * mk0[mt] + f3.y * mk1[mt];
            }
        // pool partial reduce over qrow (lanes sharing qcol): xor 4, 8, 16
        #pragma unroll
        for (int k = 0; k < 4; ++k)
            #pragma unroll
            for (int p = 0; p < 2; ++p) {
                #pragma unroll
                for (int o = 4; o <= 16; o <<= 1) {
                    pc[k][p].x += __shfl_xor_sync(0xFFFFFFFFu, pc[k][p].x, o);
                    pc[k][p].y += __shfl_xor_sync(0xFFFFFFFFu, pc[k][p].y, o);
                }
            }
        if (lane < 4) {   // qrow == 0 holds the reduced values
            #pragma unroll
            for (int k = 0; k < 4; ++k) {
                *(float2*)&sm[OFF_PART + warp * 64 + k * 16 + 2 * qcol]     = pc[k][0];
                *(float2*)&sm[OFF_PART + warp * 64 + k * 16 + 8 + 2 * qcol] = pc[k][1];
            }
        }

        // K projection: B-frags from gmem (__ldg, 2 KB table, L1-hot)
        {
            uint32_t bf[4][2];
            #pragma unroll
            for (int ktg = 0; ktg < 4; ++ktg) {
                int d0 = ktg * 16 + 2 * qcol;
                bf[ktg][0] = packh2(__ldg(Wk + d0 * 8 + qrow),       __ldg(Wk + (d0 + 1) * 8 + qrow));
                bf[ktg][1] = packh2(__ldg(Wk + (d0 + 8) * 8 + qrow), __ldg(Wk + (d0 + 9) * 8 + qrow));
            }
            float cc[4][4] = {{0,0,0,0},{0,0,0,0},{0,0,0,0},{0,0,0,0}};
            #pragma unroll
            for (int ktg = 0; ktg < 4; ++ktg)
                #pragma unroll
                for (int mt = 0; mt < 4; ++mt)
                    mma_f16(cc[mt], Af[mt][ktg], bf[ktg][0], bf[ktg][1]);
            #pragma unroll
            for (int mt = 0; mt < 4; ++mt) {
                int row = r0 + mt * 16 + qrow;
                smu[OFF_KV + row * 12 + qcol]       = packh2(cc[mt][0], cc[mt][1]);
                smu[OFF_KV + (row + 8) * 12 + qcol] = packh2(cc[mt][2], cc[mt][3]);
            }
        }
        // V projection
        {
            uint32_t bf[4][2];
            #pragma unroll
            for (int ktg = 0; ktg < 4; ++ktg) {
                int d0 = ktg * 16 + 2 * qcol;
                bf[ktg][0] = packh2(__ldg(Wv + d0 * 8 + qrow),       __ldg(Wv + (d0 + 1) * 8 + qrow));
                bf[ktg][1] = packh2(__ldg(Wv + (d0 + 8) * 8 + qrow), __ldg(Wv + (d0 + 9) * 8 + qrow));
            }
            float cc[4][4] = {{0,0,0,0},{0,0,0,0},{0,0,0,0},{0,0,0,0}};
            #pragma unroll
            for (int ktg = 0; ktg < 4; ++ktg)
                #pragma unroll
                for (int mt = 0; mt < 4; ++mt)
                    mma_f16(cc[mt], Af[mt][ktg], bf[ktg][0], bf[ktg][1]);
            #pragma unroll
            for (int mt = 0; mt < 4; ++mt) {
                int row = r0 + mt * 16 + qrow;
                smu[OFF_KV + row * 12 + 4 + qcol]       = packh2(cc[mt][0], cc[mt][1]);
                smu[OFF_KV + (row + 8) * 12 + 4 + qcol] = packh2(cc[mt][2], cc[mt][3]);
            }
        }
    }
    __syncthreads();   // B2: KV, PART, bias, Wg/Wo frags, ms ready

    // ---------- Phase 2: per-warp pool + q (redundant across warps) ----------
    float qv[8];
    {
        float p0 = 0.f, p1 = 0.f;
        #pragma unroll
        for (int w = 0; w < 8; ++w) {
            p0 += sm[OFF_PART + w * 64 + lane];
            p1 += sm[OFF_PART + w * 64 + lane + 32];
        }
        sm[OFF_POOL + lane]      = p0;   // all warps write identical values (benign)
        sm[OFF_POOL + lane + 32] = p1;
        float ms = sm[OFF_MS];
        __syncwarp();
        const int c = lane & 7, qr = lane >> 3;   // lane -> (col, d-quarter)
        float acc = 0.f;
        #pragma unroll
        for (int dd = 0; dd < 16; ++dd) {
            int d = qr * 16 + dd;
            acc += sm[OFF_POOL + d] * __ldg(&Wq[d * 64 + warp * 8 + c]);
        }
        acc += __shfl_xor_sync(0xFFFFFFFFu, acc, 8);
        acc += __shfl_xor_sync(0xFFFFFFFFu, acc, 16);
        float qs = 0.35355339059327373f / (ms + 1e-10f);
        if (lane < 8) sm[OFF_QH + warp * 8 + lane] = acc * qs;
        __syncwarp();
        #pragma unroll
        for (int cc = 0; cc < 8; ++cc) qv[cc] = sm[OFF_QH + warp * 8 + cc];
    }

    // ---------- Phase 3: attention (warp = head) with LDS.128 K/V ----------
    {
        const uint4* kvp = (const uint4*)(smu + OFF_KV);   // 16B-aligned; row = 3 uint4
        float sum = 0.f;
        float oa[8] = {0,0,0,0,0,0,0,0};
        #pragma unroll
        for (int i = 0; i < 16; ++i) {
            int r = i * 32 + lane;
            uint4 kw = kvp[r * 3];         // K: 4 x half2
            uint4 vw = kvp[r * 3 + 1];     // V: 4 x half2
            float bias = sm[OFF_BIAS + r]; // conflict-free (banks = lane)
            float2 k0 = h2f2(kw.x), k1 = h2f2(kw.y), k2 = h2f2(kw.z), k3 = h2f2(kw.w);
            float a = qv[0]*k0.x + qv[1]*k0.y + qv[2]*k1.x + qv[3]*k1.y
                    + qv[4]*k2.x + qv[5]*k2.y + qv[6]*k3.x + qv[7]*k3.y + bias;
            float p = __expf(a);
            sum += p;
            float2 v0 = h2f2(vw.x), v1 = h2f2(vw.y), v2 = h2f2(vw.z), v3 = h2f2(vw.w);
            oa[0] += p * v0.x; oa[1] += p * v0.y; oa[2] += p * v1.x; oa[3] += p * v1.y;
            oa[4] += p * v2.x; oa[5] += p * v2.y; oa[6] += p * v3.x; oa[7] += p * v3.y;
        }
        #pragma unroll
        for (int o = 16; o; o >>= 1) sum += __shfl_xor_sync(0xFFFFFFFFu, sum, o);
        #pragma unroll
        for (int c = 0; c < 8; ++c) {
            #pragma unroll
            for (int o = 16; o; o >>= 1) oa[c] += __shfl_xor_sync(0xFFFFFFFFu, oa[c], o);
        }
        if (lane == 0) {
            float inv = 1.f / sum;
            #pragma unroll
            for (int c = 0; c < 8; ++c) sm[OFF_OF + warp * 8 + c] = oa[c] * inv;
        }
    }
    __syncthreads();   // B3: OF ready for all warps

    // ---------- Phase 4: gate + output GEMM; Af in regs, h register-resident ----------
    float* outs = out + (size_t)s * (RR * 64);
    #pragma unroll
    for (int mh = 0; mh < 2; ++mh) {
        uint32_t Ah[2][4][4];
        #pragma unroll
        for (int kh = 0; kh < 4; ++kh) {
            #pragma unroll
            for (int sub = 0; sub < 2; ++sub) {
                const int nt = 2 * kh + sub;
                float cg[2][4] = {{0,0,0,0},{0,0,0,0}};
                #pragma unroll
                for (int ktg = 0; ktg < 4; ++ktg) {
                    uint32_t b0 = smu[OFF_WGF + ((nt * 4 + ktg) * 32 + lane) * 2];
                    uint32_t b1 = smu[OFF_WGF + ((nt * 4 + ktg) * 32 + lane) * 2 + 1];
                    #pragma unroll
                    for (int mt2 = 0; mt2 < 2; ++mt2)
                        mma_f16(cg[mt2], Af[mh * 2 + mt2][ktg], b0, b1);
                }
                const int col0 = nt * 8 + 2 * qcol;
                float hof0 = 0.5f * sm[OFF_OF + col0], hof1 = 0.5f * sm[OFF_OF + col0 + 1];
                float hbg0 = 0.5f * sm[OFF_BG + col0], hbg1 = 0.5f * sm[OFF_BG + col0 + 1];
                #pragma unroll
                for (int mt2 = 0; mt2 < 2; ++mt2) {
                    float h0 = fmaf(hof0, tanh_fast(fmaf(0.5f, cg[mt2][0], hbg0)), hof0);
                    float h1 = fmaf(hof1, tanh_fast(fmaf(0.5f, cg[mt2][1], hbg1)), hof1);
                    float h2 = fmaf(hof0, tanh_fast(fmaf(0.5f, cg[mt2][2], hbg0)), hof0);
                    float h3 = fmaf(hof1, tanh_fast(fmaf(0.5f, cg[mt2][3], hbg1)), hof1);
                    Ah[mt2][kh][sub * 2]     = packh2(h0, h1);
                    Ah[mt2][kh][sub * 2 + 1] = packh2(h2, h3);
                }
            }
        }
        #pragma unroll
        for (int nt = 0; nt < 8; ++nt) {
            float co[2][4] = {{0,0,0,0},{0,0,0,0}};
            #pragma unroll
            for (int kh = 0; kh < 4; ++kh) {
                uint32_t b0 = smu[OFF_WOF + ((nt * 4 + kh) * 32 + lane) * 2];
                uint32_t b1 = smu[OFF_WOF + ((nt * 4 + kh) * 32 + lane) * 2 + 1];
                #pragma unroll
                for (int mt2 = 0; mt2 < 2; ++mt2)
                    mma_f16(co[mt2], Ah[mt2][kh], b0, b1);
            }
            const int col0 = nt * 8 + 2 * qcol;
            float bo0 = sm[OFF_BO + col0], bo1 = sm[OFF_BO + col0 + 1];
            #pragma unroll
            for (int mt2 = 0; mt2 < 2; ++mt2) {
                int row = r0 + (mh * 2 + mt2) * 16 + qrow;
                *(float2*)&outs[row * 64 + col0]       = make_float2(co[mt2][0] + bo0, co[mt2][1] + bo1);
                *(float2*)&outs[(row + 8) * 64 + col0] = make_float2(co[mt2][2] + bo0, co[mt2][3] + bo1);
            }
        }
    }
}

extern "C" void kernel_launch(void* const* d_in, const int* in_sizes, int n_in,
                              void* d_out, int out_size) {
    (void)in_sizes; (void)n_in; (void)out_size;
    const float* m    = (const float*)d_in[0];
    const float* mask = (const float*)d_in[1];
    const float* Wq   = (const float*)d_in[2];
    const float* Wk   = (const float*)d_in[3];
    const float* Wv   = (const float*)d_in[4];
    const float* Wg   = (const float*)d_in[5];
    const float* bg   = (const float*)d_in[6];
    const float* Wo   = (const float*)d_in[7];
    const float* bo   = (const float*)d_in[8];
    float* out = (float*)d_out;

    cudaFuncSetAttribute(ga_kernel, cudaFuncAttributeMaxDynamicSharedMemorySize, SMEM_BYTES);
    ga_kernel<<<SS, NT, SMEM_BYTES>>>(m, mask, Wq, Wk, Wv, Wg, bg, Wo, bo, out);
}